// round 13
// baseline (speedup 1.0000x reference)
#include <cuda_runtime.h>
#include <math.h>

// Fixed problem shapes: b=8, n=4096, c=32, g=4, rad=4, rank=2, k=128, in=1024, OUT=1024
#define BB    8
#define CC    32
#define GG    4
#define RADR  4
#define KK    128
#define PPC   12          // 4 neighbor + 4 sampled + 4 range-restricted
#define NP    384         // CC * PPC points per (b,k) tile
#define INSZ  1024
#define OUTSZ 1024
#define NWARP 12          // NP/32
#define HSZ   1024        // dup-hash: 0.375 load -> ~1.8 probes (512 costs +8us, R8-R10)

// sqrt(0.5 * log2(e)) — folds the -0.5 and exp->exp2 into the inverse sigmas.
#define SQRT_HALF_LOG2E 0.8493218383f

__device__ __forceinline__ float ex2_approx(float v) {
    float r;
    asm("ex2.approx.f32 %0, %1;" : "=f"(r) : "f"(v));
    return r;
}

__global__ __launch_bounds__(NP, 4) void sparse_layer_kernel(
    const float* __restrict__ x,        // (8, 1024)
    const float* __restrict__ means,    // (8, 4096, 2)
    const float* __restrict__ sigmas,   // (8, 4096, 2)
    const float* __restrict__ values,   // (8, 4096)
    const float* __restrict__ su,       // (8, 128, 32, 4, 2)
    const float* __restrict__ ru,       // (8, 128, 32, 4, 2)
    float* __restrict__ out)            // (8, 1024)
{
    __shared__ float  sm0[CC], sm1[CC];
    __shared__ float4 scell[CC];            // (v0, v1, m0*v0, m1*v1)
    __shared__ float  sval[CC], svalw[CC];
    __shared__ float2 spts[NP];             // (p0 or 1e30 if dup, p1)
    __shared__ float  spart[NWARP * CC];
    __shared__ unsigned int tab[HSZ];       // hash: (id<<9)|ord, EMPTY=~0

    const int bk = blockIdx.x;              // b*128 + k
    const int b  = bk >> 7;
    const int t  = threadIdx.x;
    const int w  = t >> 5;
    const int l  = t & 31;

    // ---- init hash + load per-cell params ----
    #pragma unroll
    for (int i = t; i < HSZ; i += NP) tab[i] = 0xFFFFFFFFu;
    if (t < CC) {
        int base = (bk * CC + t) * 2;
        float m0 = means[base], m1 = means[base + 1];
        float v0 = sqrtf(1.0f / (1e-6f + sigmas[base]))     * SQRT_HALF_LOG2E;
        float v1 = sqrtf(1.0f / (1e-6f + sigmas[base + 1])) * SQRT_HALF_LOG2E;
        sm0[t] = m0;
        sm1[t] = m1;
        scell[t] = make_float4(v0, v1, m0 * v0, m1 * v1);
        sval[t] = values[bk * CC + t];
    }
    __syncthreads();

    // ---- tuple generation, SLOT-MAJOR: warp w = slot j, lane = cell c ----
    // Warps are branch-uniform: warps 0-3 neighbor, 4-7 sampled, 8-11 rr.
    const int j = w;                        // slot in [0,12)
    const int c = l;                        // cell in [0,32)
    int id;
    {
        const float m0v = sm0[c], m1v = sm1[c];
        const float SCL = 1.0f - 1e-6f;
        int i0, i1;
        if (j < 4) {
            // fm order (itertools.product([T,F],2)): True->floor
            i0 = (j & 2) ? (int)ceilf(m0v) : (int)floorf(m0v);
            i1 = (j & 1) ? (int)ceilf(m1v) : (int)floorf(m1v);
        } else if (j < 8) {
            int idx = ((bk * CC + c) * GG + (j - 4)) * 2;
            i0 = (int)floorf(__fmul_rn(__fmul_rn(su[idx],     SCL), 1024.0f));
            i1 = (int)floorf(__fmul_rn(__fmul_rn(su[idx + 1], SCL), 1024.0f));
        } else {
            int idx = ((bk * CC + c) * RADR + (j - 8)) * 2;
            float mn0 = rintf(m0v), mn1 = rintf(m1v);   // round half-even (jnp.round)
            float lo0 = mn0 - 8.0f, lo1 = mn1 - 8.0f;
            if (lo0 < 0.0f) lo0 = 0.0f;
            if (mn0 + 8.0f > 1024.0f) lo0 = 1008.0f;
            if (lo1 < 0.0f) lo1 = 0.0f;
            if (mn1 + 8.0f > 1024.0f) lo1 = 1008.0f;
            i0 = (int)floorf(__fadd_rn(__fmul_rn(__fmul_rn(ru[idx],     SCL), 16.0f), lo0));
            i1 = (int)floorf(__fadd_rn(__fmul_rn(__fmul_rn(ru[idx + 1], SCL), 16.0f), lo1));
        }
        id = (i0 << 10) | i1;
    }

    // ---- duplicate marking via shared hash (first occurrence in reference
    //      order ord = c*12 + j wins — matches stable-argsort semantics) ----
    bool dup;
    {
        const unsigned int ord = (unsigned int)(c * PPC + j);    // < 384, 9 bits
        const unsigned int uid = (unsigned int)id;
        const unsigned int val = (uid << 9) | ord;
        unsigned int h = (uid * 2654435761u) >> 22;              // top 10 bits
        int slot;
        for (;;) {
            unsigned int old = atomicCAS(&tab[h], 0xFFFFFFFFu, val);
            if (old == 0xFFFFFFFFu) { slot = h; break; }
            if ((old >> 9) == uid)  { atomicMin(&tab[h], val); slot = h; break; }
            h = (h + 1) & (HSZ - 1);
        }
        __syncthreads();
        dup = ((tab[slot] & 511u) != ord);
        // dup -> p0 = 1e30 => ex2 arg -> -inf => density exactly 0
        spts[t] = make_float2(dup ? 1e30f : (float)(id >> 10), (float)(id & 1023));
    }
    __syncthreads();

    // ---- single density pass: warp w owns ITS OWN lanes' 32 points, lane = cell.
    //      e[ii] kept in registers; colsum partials accumulated on the fly. ----
    float e[32];
    {
        const float4 cp = scell[l];
        float c0 = 0.0f, c1 = 0.0f;
        #pragma unroll
        for (int ii = 0; ii < 32; ii += 2) {
            float2 pa = spts[(w << 5) + ii];        // LDS.64 broadcast
            float2 pb = spts[(w << 5) + ii + 1];
            float a0 = __fmaf_rn(pa.x, cp.x, -cp.z), a1 = __fmaf_rn(pa.y, cp.y, -cp.w);
            float b0 = __fmaf_rn(pb.x, cp.x, -cp.z), b1 = __fmaf_rn(pb.y, cp.y, -cp.w);
            float ea = ex2_approx(__fmaf_rn(-a1, a1, __fmul_rn(-a0, a0)));
            float eb = ex2_approx(__fmaf_rn(-b1, b1, __fmul_rn(-b0, b0)));
            e[ii]     = ea;
            e[ii + 1] = eb;
            c0 += ea;
            c1 += eb;
        }
        spart[w * CC + l] = c0 + c1;
    }
    __syncthreads();

    // ---- column totals -> value/colsum weights ----
    if (t < CC) {
        float s = 0.0f;
        #pragma unroll
        for (int ww = 0; ww < NWARP; ++ww) s += spart[ww * CC + t];
        svalw[t] = sval[t] / s;
    }
    __syncthreads();

    // ---- weight by svalw[cell] and 32x32 register transpose-reduce:
    //      afterwards e[0] on lane l = Σ_cells w(point (w<<5)+l, cell) ----
    {
        const float vwl = svalw[l];
        #pragma unroll
        for (int ii = 0; ii < 32; ++ii) e[ii] *= vwl;

        #pragma unroll
        for (int mask = 16; mask >= 1; mask >>= 1) {
            const bool hi = (l & mask) != 0;
            #pragma unroll
            for (int jj = 0; jj < mask; ++jj) {
                float a = e[jj], bq = e[jj + mask];
                float keep = hi ? bq : a;
                float give = hi ? a : bq;
                e[jj] = keep + __shfl_xor_sync(0xffffffffu, give, mask);
            }
        }
    }

    // ---- scatter: point (w<<5)+l IS this thread's own point (id, dup in regs) ----
    if (!dup) {
        float contrib = e[0] * x[b * INSZ + (id & 1023)];
        atomicAdd(&out[b * OUTSZ + ((id >> 10) & 1023)], contrib);
    }
}

extern "C" void kernel_launch(void* const* d_in, const int* in_sizes, int n_in,
                              void* d_out, int out_size)
{
    const float* x      = (const float*)d_in[0];
    const float* means  = (const float*)d_in[1];
    const float* sigmas = (const float*)d_in[2];
    const float* values = (const float*)d_in[3];
    const float* su     = (const float*)d_in[4];
    const float* ru     = (const float*)d_in[5];
    float* out = (float*)d_out;

    cudaMemsetAsync(out, 0, (size_t)out_size * sizeof(float));
    sparse_layer_kernel<<<BB * KK, NP>>>(x, means, sigmas, values, su, ru, out);
}